// round 15
// baseline (speedup 1.0000x reference)
#include <cuda_runtime.h>
#include <cuda_bf16.h>
#include <math.h>
#include <stdint.h>

#define BB   16
#define LL   1024
#define DD   384
#define FF   1536
#define TOUT 10240
#define MAXDUR 10

// ---------------------------------------------------------------------------
// Scratch (device globals: allocation-free rule)
__device__ __nv_bfloat16 g_ys  [3ull*BB*LL*DD];
__device__ __nv_bfloat16 g_h1as[3ull*BB*LL*FF];
__device__ __nv_bfloat16 g_h1ns[3ull*BB*LL*DD];
__device__ __nv_bfloat16 g_h2as[3ull*BB*LL*FF];
__device__ float g_h1b[BB*LL*DD];
__device__ float g_h2b[BB*LL*DD];
__device__ __nv_bfloat16 g_w1as[3ull*FF*3*DD];
__device__ __nv_bfloat16 g_w1bs[3ull*DD*3*FF];
__device__ __nv_bfloat16 g_w2as[3ull*FF*3*DD];
__device__ __nv_bfloat16 g_w2bs[3ull*DD*3*FF];
__device__ int g_lns[BB*LL];
__device__ int g_csum[BB*LL];
__device__ int g_tot[BB];

// ---------------------------------------------------------------------------
__device__ __forceinline__ void split3(float x, __nv_bfloat16& b0,
                                       __nv_bfloat16& b1, __nv_bfloat16& b2) {
    b0 = __float2bfloat16(x);
    float r = x - __bfloat162float(b0);
    b1 = __float2bfloat16(r);
    float r2 = r - __bfloat162float(b1);
    b2 = __float2bfloat16(r2);
}
__device__ __forceinline__ uint32_t packbf(__nv_bfloat16 lo, __nv_bfloat16 hi) {
    return (uint32_t)__bfloat16_as_ushort(lo) | ((uint32_t)__bfloat16_as_ushort(hi) << 16);
}

// mma.sync m16n8k16 row.col f32 += bf16*bf16  (fragment map validated in R11/R13)
__device__ __forceinline__ void mma16816(float* c, const uint32_t* a, const uint32_t* b) {
    asm volatile(
        "mma.sync.aligned.m16n8k16.row.col.f32.bf16.bf16.f32 "
        "{%0,%1,%2,%3}, {%4,%5,%6,%7}, {%8,%9}, {%0,%1,%2,%3};"
        : "+f"(c[0]), "+f"(c[1]), "+f"(c[2]), "+f"(c[3])
        : "r"(a[0]), "r"(a[1]), "r"(a[2]), "r"(a[3]), "r"(b[0]), "r"(b[1]));
}

// TwoSum compensated accumulate: (s, e) += c   (exact error capture)
__device__ __forceinline__ void twosum(float& s, float& e, float c) {
    float t  = s + c;
    float bv = t - s;
    float av = t - bv;
    e += (s - av) + (c - bv);
    s = t;
}

// ---------------------------------------------------------------------------
__global__ __launch_bounds__(256)
void split_kernel(const float* __restrict__ x, __nv_bfloat16* __restrict__ out,
                  size_t n, size_t stride)
{
    size_t i = (size_t)blockIdx.x * 256 + threadIdx.x;
    if (i >= n) return;
    __nv_bfloat16 b0, b1, b2;
    split3(x[i], b0, b1, b2);
    out[i] = b0; out[stride + i] = b1; out[2 * stride + i] = b2;
}

// w[co][ci*3+k] -> out[sp][co][k*CIN+ci]
__global__ __launch_bounds__(256)
void wsplit_kernel(const float* __restrict__ w, __nv_bfloat16* __restrict__ out,
                   int cin, int cout)
{
    int co = blockIdx.x;
    size_t KT = (size_t)3 * cin;
    size_t STR = (size_t)cout * KT;
    for (int t = threadIdx.x; t < 3 * cin; t += 256) {
        int k = t / cin, ci = t - k * cin;
        float x = w[(size_t)co * KT + (size_t)ci * 3 + k];
        __nv_bfloat16 b0, b1, b2;
        split3(x, b0, b1, b2);
        size_t o = (size_t)co * KT + t;
        out[o] = b0; out[STR + o] = b1; out[2 * STR + o] = b2;
    }
}

// ---------------------------------------------------------------------------
// HMMA conv with compensated accumulation:
// D[l, co] = relu(bias + sum_{r'} A[l, r'] * W[co, r'])
// r' = k*CIN+ci ; A[l, r'] = in[l+k-1, ci] (im2col). fp32 = bf16x3,
// 8 products (all (i,j) except (2,2)). Chunk-local fp32 HMMA accumulators,
// drained every 64 K into TwoSum (s,e) pairs -> cross-chunk error ~2^-48.
// Block 128(l) x 32(co), 8 warps (4m x 2n), warp tile 32x16 (2x2 m16n8k16).
// ---------------------------------------------------------------------------
template<int CIN, int COUT, bool SPLIT_OUT>
__global__ __launch_bounds__(256)
void conv_mma_kernel(const __nv_bfloat16* __restrict__ Asp,
                     const __nv_bfloat16* __restrict__ Wsp,
                     const float* __restrict__ bias,
                     float* __restrict__ outF,
                     __nv_bfloat16* __restrict__ outS,
                     const int* __restrict__ tlen, int margin)
{
    constexpr int KT  = 3 * CIN;
    constexpr int NCH = KT / 32;          // 36 or 144 (even)

    __shared__ __nv_bfloat16 As[3][128][40];   // [sp][l][k]
    __shared__ __nv_bfloat16 Bs[3][32][40];    // [sp][co][k]

    const int tid  = threadIdx.x;
    const int wid  = tid >> 5;
    const int lane = tid & 31;
    const int grp  = lane >> 2;
    const int q    = lane & 3;
    const int wm   = wid & 3;      // 0..3 : rows wm*32
    const int wn   = wid >> 2;     // 0..1 : cols wn*16

    const int b     = blockIdx.z;
    const int lbase = blockIdx.x * 128;
    const int cbase = blockIdx.y * 32;
    int limit = tlen[b] + margin; if (limit > LL) limit = LL;
    if (lbase >= limit) return;

    float sm[2][2][4], er[2][2][4];
#pragma unroll
    for (int mt = 0; mt < 2; mt++)
#pragma unroll
        for (int nt = 0; nt < 2; nt++)
#pragma unroll
            for (int r = 0; r < 4; r++) { sm[mt][nt][r] = 0.f; er[mt][nt][r] = 0.f; }

    const size_t ASTR = (size_t)BB * LL * CIN;
    const size_t WSTR = (size_t)COUT * KT;
    const __nv_bfloat16* Ab = Asp + (size_t)b * LL * CIN;

    for (int kc2 = 0; kc2 < NCH; kc2 += 2) {
        float cs[2][2][4];
#pragma unroll
        for (int mt = 0; mt < 2; mt++)
#pragma unroll
            for (int nt = 0; nt < 2; nt++)
#pragma unroll
                for (int r = 0; r < 4; r++) cs[mt][nt][r] = 0.f;

#pragma unroll
        for (int kci = 0; kci < 2; kci++) {
            const int kc   = kc2 + kci;
            const int rb   = kc * 32;
            const int ktap = rb / CIN;
            const int ci0  = rb - ktap * CIN;

            // A tiles: 3 sp x 128 rows x 32 k (uint4 = 8 bf16)
#pragma unroll
            for (int i = tid; i < 1536; i += 256) {
                int sp = i >> 9, rem = i & 511;
                int ll = rem >> 2, v = rem & 3;
                int gl = lbase + ll + ktap - 1;
                uint4 x = make_uint4(0u, 0u, 0u, 0u);
                if (gl >= 0 && gl < LL)
                    x = *(const uint4*)(Ab + sp * ASTR + (size_t)gl * CIN + ci0 + v * 8);
                *(uint4*)&As[sp][ll][v * 8] = x;
            }
            // B tiles: 3 sp x 32 co x 32 k  (384 uint4)
#pragma unroll
            for (int i = tid; i < 384; i += 256) {
                int sp = i >> 7, rem = i & 127;
                int co = rem >> 2, v = rem & 3;
                uint4 x = *(const uint4*)(Wsp + sp * WSTR + (size_t)(cbase + co) * KT + rb + v * 8);
                *(uint4*)&Bs[sp][co][v * 8] = x;
            }
            __syncthreads();

#pragma unroll
            for (int ks = 0; ks < 2; ks++) {
                const int kb = ks * 16;
#pragma unroll
                for (int spb = 0; spb < 3; spb++) {
                    uint32_t bf[2][2];
#pragma unroll
                    for (int nt = 0; nt < 2; nt++) {
                        int col = wn * 16 + nt * 8 + grp;
                        bf[nt][0] = *(const uint32_t*)&Bs[spb][col][kb + q * 2];
                        bf[nt][1] = *(const uint32_t*)&Bs[spb][col][kb + q * 2 + 8];
                    }
#pragma unroll
                    for (int spa = 0; spa < 3; spa++) {
                        if (spa + spb >= 4) continue;   // drop only (2,2)
                        uint32_t af[2][4];
#pragma unroll
                        for (int mt = 0; mt < 2; mt++) {
                            int row = wm * 32 + mt * 16 + grp;
                            af[mt][0] = *(const uint32_t*)&As[spa][row][kb + q * 2];
                            af[mt][1] = *(const uint32_t*)&As[spa][row + 8][kb + q * 2];
                            af[mt][2] = *(const uint32_t*)&As[spa][row][kb + q * 2 + 8];
                            af[mt][3] = *(const uint32_t*)&As[spa][row + 8][kb + q * 2 + 8];
                        }
#pragma unroll
                        for (int mt = 0; mt < 2; mt++)
#pragma unroll
                            for (int nt = 0; nt < 2; nt++)
                                mma16816(cs[mt][nt], af[mt], bf[nt]);
                    }
                }
            }
            __syncthreads();
        }

        // drain chunk pair into compensated accumulators
#pragma unroll
        for (int mt = 0; mt < 2; mt++)
#pragma unroll
            for (int nt = 0; nt < 2; nt++)
#pragma unroll
                for (int r = 0; r < 4; r++)
                    twosum(sm[mt][nt][r], er[mt][nt][r], cs[mt][nt][r]);
    }

    // ---- epilogue: bias + relu, direct from compensated accumulators ----
    const size_t OSTR = (size_t)BB * LL * COUT;
#pragma unroll
    for (int mt = 0; mt < 2; mt++) {
#pragma unroll
        for (int nt = 0; nt < 2; nt++) {
            int cc = cbase + wn * 16 + nt * 8 + q * 2;
            float bz0 = bias[cc], bz1 = bias[cc + 1];
            int r0 = lbase + wm * 32 + mt * 16 + grp;
#pragma unroll
            for (int h = 0; h < 2; h++) {
                int r = r0 + h * 8;
                float v0 = fmaxf((sm[mt][nt][2 * h + 0] + er[mt][nt][2 * h + 0]) + bz0, 0.f);
                float v1 = fmaxf((sm[mt][nt][2 * h + 1] + er[mt][nt][2 * h + 1]) + bz1, 0.f);
                size_t o = ((size_t)b * LL + r) * COUT + cc;
                if (SPLIT_OUT) {
                    __nv_bfloat16 a0, a1, a2, d0, d1, d2;
                    split3(v0, a0, a1, a2);
                    split3(v1, d0, d1, d2);
                    *(uint32_t*)(outS + o)            = packbf(a0, d0);
                    *(uint32_t*)(outS + OSTR + o)     = packbf(a1, d1);
                    *(uint32_t*)(outS + 2 * OSTR + o) = packbf(a2, d2);
                } else {
                    *(float2*)(outF + o) = make_float2(v0, v1);
                }
            }
        }
    }
}

// ---------------------------------------------------------------------------
__global__ __launch_bounds__(256)
void ln_split_kernel(const float* __restrict__ in, const float* __restrict__ g,
                     const float* __restrict__ be, __nv_bfloat16* __restrict__ out,
                     const int* __restrict__ tlen, int margin)
{
    int b = blockIdx.y;
    int l = blockIdx.x * 8 + (threadIdx.x >> 5);
    int lane = threadIdx.x & 31;
    int limit = tlen[b] + margin; if (limit > LL) limit = LL;
    if (l >= limit) return;

    const size_t STR = (size_t)BB * LL * DD;
    size_t base = ((size_t)b * LL + l) * DD;
    float x[12];
#pragma unroll
    for (int i = 0; i < 12; i++) x[i] = in[base + lane + 32 * i];
    float s = 0.f;
#pragma unroll
    for (int i = 0; i < 12; i++) s += x[i];
#pragma unroll
    for (int o = 16; o > 0; o >>= 1) s += __shfl_xor_sync(0xffffffffu, s, o);
    float mu = s * (1.f / DD);
    float qv = 0.f;
#pragma unroll
    for (int i = 0; i < 12; i++) { float d = x[i] - mu; qv += d * d; }
#pragma unroll
    for (int o = 16; o > 0; o >>= 1) qv += __shfl_xor_sync(0xffffffffu, qv, o);
    float rstd = 1.f / sqrtf(qv * (1.f / DD) + 1e-5f);
#pragma unroll
    for (int i = 0; i < 12; i++) {
        int d = lane + 32 * i;
        float v = (x[i] - mu) * rstd * g[d] + be[d];
        __nv_bfloat16 b0, b1, b2;
        split3(v, b0, b1, b2);
        out[base + d] = b0; out[STR + base + d] = b1; out[2 * STR + base + d] = b2;
    }
}

// ---------------------------------------------------------------------------
__global__ __launch_bounds__(256)
void pred_kernel(const float* __restrict__ in, const float* __restrict__ g,
                 const float* __restrict__ be, const float* __restrict__ wl,
                 const float* __restrict__ bl, const int* __restrict__ tlen,
                 int* __restrict__ lns)
{
    int b = blockIdx.y;
    int l = blockIdx.x * 8 + (threadIdx.x >> 5);
    int lane = threadIdx.x & 31;
    if (l >= tlen[b]) { if (lane == 0) lns[b * LL + l] = 0; return; }

    size_t base = ((size_t)b * LL + l) * DD;
    float x[12];
#pragma unroll
    for (int i = 0; i < 12; i++) x[i] = in[base + lane + 32 * i];
    float s = 0.f;
#pragma unroll
    for (int i = 0; i < 12; i++) s += x[i];
#pragma unroll
    for (int o = 16; o > 0; o >>= 1) s += __shfl_xor_sync(0xffffffffu, s, o);
    float mu = s * (1.f / DD);
    float qv = 0.f;
#pragma unroll
    for (int i = 0; i < 12; i++) { float d = x[i] - mu; qv += d * d; }
#pragma unroll
    for (int o = 16; o > 0; o >>= 1) qv += __shfl_xor_sync(0xffffffffu, qv, o);
    float rstd = 1.f / sqrtf(qv * (1.f / DD) + 1e-5f);
    float p = 0.f;
#pragma unroll
    for (int i = 0; i < 12; i++) {
        int d = lane + 32 * i;
        p += ((x[i] - mu) * rstd * g[d] + be[d]) * wl[d];
    }
#pragma unroll
    for (int o = 16; o > 0; o >>= 1) p += __shfl_xor_sync(0xffffffffu, p, o);
    if (lane == 0) {
        float e = expf(p + bl[0]);
        float r = rintf(e);
        if (r > (float)MAXDUR) r = (float)MAXDUR;
        lns[b * LL + l] = (int)r;
    }
}

// ---------------------------------------------------------------------------
__global__ __launch_bounds__(1024)
void scan_kernel(const int* __restrict__ lns, int* __restrict__ csum,
                 int* __restrict__ tot, float* __restrict__ out_tail, int write_tail)
{
    __shared__ int s[1024];
    int b = blockIdx.x, t = threadIdx.x;
    s[t] = lns[b * LL + t];
    __syncthreads();
    for (int o = 1; o < 1024; o <<= 1) {
        int v = (t >= o) ? s[t - o] : 0;
        __syncthreads();
        s[t] += v;
        __syncthreads();
    }
    csum[b * LL + t] = s[t];
    if (t == 1023) {
        tot[b] = s[t];
        if (write_tail) out_tail[b] = (float)s[t];
    }
}

// ---------------------------------------------------------------------------
__global__ __launch_bounds__(256)
void gather_kernel(const float* __restrict__ y, const int* __restrict__ csum,
                   const int* __restrict__ tot, float* __restrict__ out)
{
    int b = blockIdx.y;
    int t = blockIdx.x * 8 + (threadIdx.x >> 5);
    int lane = threadIdx.x & 31;

    int idx = 0;
    if (lane == 0) {
        const int* c = csum + b * LL;
        int lo = 0, hi = LL;
        while (lo < hi) { int mid = (lo + hi) >> 1; if (c[mid] <= t) lo = mid + 1; else hi = mid; }
        idx = (lo < LL - 1) ? lo : (LL - 1);
    }
    idx = __shfl_sync(0xffffffffu, idx, 0);
    bool valid = t < tot[b];

    const float4* src = (const float4*)(y + ((size_t)b * LL + idx) * DD);
    float4*       dst = (float4*)(out + ((size_t)b * TOUT + t) * DD);
    float4 z = make_float4(0.f, 0.f, 0.f, 0.f);
#pragma unroll
    for (int i = 0; i < 3; i++) dst[lane + 32 * i] = valid ? src[lane + 32 * i] : z;
}

// ---------------------------------------------------------------------------
extern "C" void kernel_launch(void* const* d_in, const int* in_sizes, int n_in,
                              void* d_out, int out_size)
{
    const float* y    = (const float*)d_in[0];
    const int*   tlen = (const int*)  d_in[1];
    const float* w1a  = (const float*)d_in[2];
    const float* b1a  = (const float*)d_in[3];
    const float* w1b  = (const float*)d_in[4];
    const float* b1b  = (const float*)d_in[5];
    const float* g1   = (const float*)d_in[6];
    const float* be1  = (const float*)d_in[7];
    const float* w2a  = (const float*)d_in[8];
    const float* b2a  = (const float*)d_in[9];
    const float* w2b  = (const float*)d_in[10];
    const float* b2b  = (const float*)d_in[11];
    const float* g2   = (const float*)d_in[12];
    const float* be2  = (const float*)d_in[13];
    const float* wl   = (const float*)d_in[14];
    const float* bl   = (const float*)d_in[15];
    float* out = (float*)d_out;

    __nv_bfloat16 *ys, *h1as, *h1ns, *h2as, *w1as, *w1bs, *w2as, *w2bs;
    float *h1b, *h2b; int *lns, *csum, *tot;
    cudaGetSymbolAddress((void**)&ys,   g_ys);
    cudaGetSymbolAddress((void**)&h1as, g_h1as);
    cudaGetSymbolAddress((void**)&h1ns, g_h1ns);
    cudaGetSymbolAddress((void**)&h2as, g_h2as);
    cudaGetSymbolAddress((void**)&w1as, g_w1as);
    cudaGetSymbolAddress((void**)&w1bs, g_w1bs);
    cudaGetSymbolAddress((void**)&w2as, g_w2as);
    cudaGetSymbolAddress((void**)&w2bs, g_w2bs);
    cudaGetSymbolAddress((void**)&h1b,  g_h1b);
    cudaGetSymbolAddress((void**)&h2b,  g_h2b);
    cudaGetSymbolAddress((void**)&lns,  g_lns);
    cudaGetSymbolAddress((void**)&csum, g_csum);
    cudaGetSymbolAddress((void**)&tot,  g_tot);

    wsplit_kernel<<<FF, 256>>>(w1a, w1as, DD, FF);
    wsplit_kernel<<<DD, 256>>>(w1b, w1bs, FF, DD);
    wsplit_kernel<<<FF, 256>>>(w2a, w2as, DD, FF);
    wsplit_kernel<<<DD, 256>>>(w2b, w2bs, FF, DD);
    {
        size_t n = (size_t)BB * LL * DD;
        split_kernel<<<(unsigned)((n + 255) / 256), 256>>>(y, ys, n, n);
    }

    dim3 gA(LL / 128, FF / 32, BB);
    dim3 gB(LL / 128, DD / 32, BB);
    dim3 gR(LL / 8, BB);

    conv_mma_kernel<DD, FF, true ><<<gA, 256>>>(ys,   w1as, b1a, nullptr, h1as, tlen, 3);
    conv_mma_kernel<FF, DD, false><<<gB, 256>>>(h1as, w1bs, b1b, h1b, nullptr, tlen, 2);
    ln_split_kernel<<<gR, 256>>>(h1b, g1, be1, h1ns, tlen, 2);
    conv_mma_kernel<DD, FF, true ><<<gA, 256>>>(h1ns, w2as, b2a, nullptr, h2as, tlen, 1);
    conv_mma_kernel<FF, DD, false><<<gB, 256>>>(h2as, w2bs, b2b, h2b, nullptr, tlen, 0);
    pred_kernel<<<gR, 256>>>(h2b, g2, be2, wl, bl, tlen, lns);

    int write_tail = (out_size >= BB * TOUT * DD + BB) ? 1 : 0;
    scan_kernel<<<BB, 1024>>>(lns, csum, tot, out + (size_t)BB * TOUT * DD, write_tail);
    gather_kernel<<<dim3(TOUT / 8, BB), 256>>>(y, csum, tot, out);
}

// round 16
// speedup vs baseline: 1.0539x; 1.0539x over previous
#include <cuda_runtime.h>
#include <cuda_bf16.h>
#include <math.h>
#include <stdint.h>

#define BB   16
#define LL   1024
#define DD   384
#define FF   1536
#define TOUT 10240
#define MAXDUR 10

// ---------------------------------------------------------------------------
// Scratch (device globals: allocation-free rule)
__device__ __nv_bfloat16 g_ys  [3ull*BB*LL*DD];
__device__ __nv_bfloat16 g_h1as[3ull*BB*LL*FF];
__device__ __nv_bfloat16 g_h1ns[3ull*BB*LL*DD];
__device__ __nv_bfloat16 g_h2as[3ull*BB*LL*FF];
__device__ float g_h1b[BB*LL*DD];
__device__ float g_h2b[BB*LL*DD];
__device__ __nv_bfloat16 g_w1as[3ull*FF*3*DD];
__device__ __nv_bfloat16 g_w1bs[3ull*DD*3*FF];
__device__ __nv_bfloat16 g_w2as[3ull*FF*3*DD];
__device__ __nv_bfloat16 g_w2bs[3ull*DD*3*FF];
__device__ int g_lns[BB*LL];
__device__ int g_csum[BB*LL];
__device__ int g_tot[BB];

// ---------------------------------------------------------------------------
__device__ __forceinline__ void split3(float x, __nv_bfloat16& b0,
                                       __nv_bfloat16& b1, __nv_bfloat16& b2) {
    b0 = __float2bfloat16(x);
    float r = x - __bfloat162float(b0);
    b1 = __float2bfloat16(r);
    float r2 = r - __bfloat162float(b1);
    b2 = __float2bfloat16(r2);
}
__device__ __forceinline__ uint32_t packbf(__nv_bfloat16 lo, __nv_bfloat16 hi) {
    return (uint32_t)__bfloat16_as_ushort(lo) | ((uint32_t)__bfloat16_as_ushort(hi) << 16);
}

// mma.sync m16n8k16 row.col f32 += bf16*bf16
__device__ __forceinline__ void mma16816(float* c, const uint32_t* a, const uint32_t* b) {
    asm volatile(
        "mma.sync.aligned.m16n8k16.row.col.f32.bf16.bf16.f32 "
        "{%0,%1,%2,%3}, {%4,%5,%6,%7}, {%8,%9}, {%0,%1,%2,%3};"
        : "+f"(c[0]), "+f"(c[1]), "+f"(c[2]), "+f"(c[3])
        : "r"(a[0]), "r"(a[1]), "r"(a[2]), "r"(a[3]), "r"(b[0]), "r"(b[1]));
}

// TwoSum compensated accumulate: (s, e) += c
__device__ __forceinline__ void twosum(float& s, float& e, float c) {
    float t  = s + c;
    float bv = t - s;
    float av = t - bv;
    e += (s - av) + (c - bv);
    s = t;
}

// ---------------------------------------------------------------------------
__global__ __launch_bounds__(256)
void split_kernel(const float* __restrict__ x, __nv_bfloat16* __restrict__ out,
                  size_t n, size_t stride)
{
    size_t i = (size_t)blockIdx.x * 256 + threadIdx.x;
    if (i >= n) return;
    __nv_bfloat16 b0, b1, b2;
    split3(x[i], b0, b1, b2);
    out[i] = b0; out[stride + i] = b1; out[2 * stride + i] = b2;
}

// w[co][ci*3+k] -> out[sp][co][k*CIN+ci]
__global__ __launch_bounds__(256)
void wsplit_kernel(const float* __restrict__ w, __nv_bfloat16* __restrict__ out,
                   int cin, int cout)
{
    int co = blockIdx.x;
    size_t KT = (size_t)3 * cin;
    size_t STR = (size_t)cout * KT;
    for (int t = threadIdx.x; t < 3 * cin; t += 256) {
        int k = t / cin, ci = t - k * cin;
        float x = w[(size_t)co * KT + (size_t)ci * 3 + k];
        __nv_bfloat16 b0, b1, b2;
        split3(x, b0, b1, b2);
        size_t o = (size_t)co * KT + t;
        out[o] = b0; out[STR + o] = b1; out[2 * STR + o] = b2;
    }
}

// ---------------------------------------------------------------------------
// HMMA conv with compensated accumulation (numerics identical to R15):
// bf16x3, 8 products (drop (2,2)); 32-K chunks, drain every 64 K via TwoSum.
// NEW: block 128(l) x 64(co), 512 threads, 16 warps (4m x 4n), warp 32x16;
// fragments hoisted once per k16 step (36 LDS per 32 MMAs).
// ---------------------------------------------------------------------------
template<int CIN, int COUT, bool SPLIT_OUT>
__global__ __launch_bounds__(512)
void conv_mma_kernel(const __nv_bfloat16* __restrict__ Asp,
                     const __nv_bfloat16* __restrict__ Wsp,
                     const float* __restrict__ bias,
                     float* __restrict__ outF,
                     __nv_bfloat16* __restrict__ outS,
                     const int* __restrict__ tlen, int margin)
{
    constexpr int KT  = 3 * CIN;
    constexpr int NCH = KT / 32;          // even

    __shared__ __nv_bfloat16 As[3][128][40];   // [sp][l][k]
    __shared__ __nv_bfloat16 Bs[3][64][40];    // [sp][co][k]

    const int tid  = threadIdx.x;
    const int wid  = tid >> 5;     // 0..15
    const int lane = tid & 31;
    const int grp  = lane >> 2;
    const int q    = lane & 3;
    const int wm   = wid & 3;      // rows wm*32
    const int wn   = wid >> 2;     // cols wn*16 (0..3)

    const int b     = blockIdx.z;
    const int lbase = blockIdx.x * 128;
    const int cbase = blockIdx.y * 64;
    int limit = tlen[b] + margin; if (limit > LL) limit = LL;
    if (lbase >= limit) return;

    float sm[2][2][4], er[2][2][4];
#pragma unroll
    for (int mt = 0; mt < 2; mt++)
#pragma unroll
        for (int nt = 0; nt < 2; nt++)
#pragma unroll
            for (int r = 0; r < 4; r++) { sm[mt][nt][r] = 0.f; er[mt][nt][r] = 0.f; }

    const size_t ASTR = (size_t)BB * LL * CIN;
    const size_t WSTR = (size_t)COUT * KT;
    const __nv_bfloat16* Ab = Asp + (size_t)b * LL * CIN;

    for (int kc2 = 0; kc2 < NCH; kc2 += 2) {
        float cs[2][2][4];
#pragma unroll
        for (int mt = 0; mt < 2; mt++)
#pragma unroll
            for (int nt = 0; nt < 2; nt++)
#pragma unroll
                for (int r = 0; r < 4; r++) cs[mt][nt][r] = 0.f;

#pragma unroll
        for (int kci = 0; kci < 2; kci++) {
            const int kc   = kc2 + kci;
            const int rb   = kc * 32;
            const int ktap = rb / CIN;
            const int ci0  = rb - ktap * CIN;

            // A tiles: 3 sp x 128 rows x 32 k (1536 uint4, 3/thread)
#pragma unroll
            for (int i = tid; i < 1536; i += 512) {
                int sp = i >> 9, rem = i & 511;
                int ll = rem >> 2, v = rem & 3;
                int gl = lbase + ll + ktap - 1;
                uint4 x = make_uint4(0u, 0u, 0u, 0u);
                if (gl >= 0 && gl < LL)
                    x = *(const uint4*)(Ab + sp * ASTR + (size_t)gl * CIN + ci0 + v * 8);
                *(uint4*)&As[sp][ll][v * 8] = x;
            }
            // B tiles: 3 sp x 64 co x 32 k (768 uint4)
#pragma unroll
            for (int i = tid; i < 768; i += 512) {
                int sp = i >> 8, rem = i & 255;
                int co = rem >> 2, v = rem & 3;
                uint4 x = *(const uint4*)(Wsp + sp * WSTR + (size_t)(cbase + co) * KT + rb + v * 8);
                *(uint4*)&Bs[sp][co][v * 8] = x;
            }
            __syncthreads();

#pragma unroll
            for (int ks = 0; ks < 2; ks++) {
                const int kb = ks * 16;
                // hoisted fragments: all 3 splits loaded ONCE per k16 step
                uint32_t af[3][2][4];
#pragma unroll
                for (int sp = 0; sp < 3; sp++)
#pragma unroll
                    for (int mt = 0; mt < 2; mt++) {
                        int row = wm * 32 + mt * 16 + grp;
                        af[sp][mt][0] = *(const uint32_t*)&As[sp][row][kb + q * 2];
                        af[sp][mt][1] = *(const uint32_t*)&As[sp][row + 8][kb + q * 2];
                        af[sp][mt][2] = *(const uint32_t*)&As[sp][row][kb + q * 2 + 8];
                        af[sp][mt][3] = *(const uint32_t*)&As[sp][row + 8][kb + q * 2 + 8];
                    }
                uint32_t bf[3][2][2];
#pragma unroll
                for (int sp = 0; sp < 3; sp++)
#pragma unroll
                    for (int nt = 0; nt < 2; nt++) {
                        int col = wn * 16 + nt * 8 + grp;
                        bf[sp][nt][0] = *(const uint32_t*)&Bs[sp][col][kb + q * 2];
                        bf[sp][nt][1] = *(const uint32_t*)&Bs[sp][col][kb + q * 2 + 8];
                    }
                // 8 products (drop (2,2))
#pragma unroll
                for (int spb = 0; spb < 3; spb++)
#pragma unroll
                    for (int spa = 0; spa < 3; spa++) {
                        if (spa + spb >= 4) continue;
#pragma unroll
                        for (int mt = 0; mt < 2; mt++)
#pragma unroll
                            for (int nt = 0; nt < 2; nt++)
                                mma16816(cs[mt][nt], af[spa][mt], bf[spb][nt]);
                    }
            }
            __syncthreads();
        }

        // drain chunk pair into compensated accumulators
#pragma unroll
        for (int mt = 0; mt < 2; mt++)
#pragma unroll
            for (int nt = 0; nt < 2; nt++)
#pragma unroll
                for (int r = 0; r < 4; r++)
                    twosum(sm[mt][nt][r], er[mt][nt][r], cs[mt][nt][r]);
    }

    // ---- epilogue: bias + relu, direct from compensated accumulators ----
    const size_t OSTR = (size_t)BB * LL * COUT;
#pragma unroll
    for (int mt = 0; mt < 2; mt++) {
#pragma unroll
        for (int nt = 0; nt < 2; nt++) {
            int cc = cbase + wn * 16 + nt * 8 + q * 2;
            float bz0 = bias[cc], bz1 = bias[cc + 1];
            int r0 = lbase + wm * 32 + mt * 16 + grp;
#pragma unroll
            for (int h = 0; h < 2; h++) {
                int r = r0 + h * 8;
                float v0 = fmaxf((sm[mt][nt][2 * h + 0] + er[mt][nt][2 * h + 0]) + bz0, 0.f);
                float v1 = fmaxf((sm[mt][nt][2 * h + 1] + er[mt][nt][2 * h + 1]) + bz1, 0.f);
                size_t o = ((size_t)b * LL + r) * COUT + cc;
                if (SPLIT_OUT) {
                    __nv_bfloat16 a0, a1, a2, d0, d1, d2;
                    split3(v0, a0, a1, a2);
                    split3(v1, d0, d1, d2);
                    *(uint32_t*)(outS + o)            = packbf(a0, d0);
                    *(uint32_t*)(outS + OSTR + o)     = packbf(a1, d1);
                    *(uint32_t*)(outS + 2 * OSTR + o) = packbf(a2, d2);
                } else {
                    *(float2*)(outF + o) = make_float2(v0, v1);
                }
            }
        }
    }
}

// ---------------------------------------------------------------------------
__global__ __launch_bounds__(256)
void ln_split_kernel(const float* __restrict__ in, const float* __restrict__ g,
                     const float* __restrict__ be, __nv_bfloat16* __restrict__ out,
                     const int* __restrict__ tlen, int margin)
{
    int b = blockIdx.y;
    int l = blockIdx.x * 8 + (threadIdx.x >> 5);
    int lane = threadIdx.x & 31;
    int limit = tlen[b] + margin; if (limit > LL) limit = LL;
    if (l >= limit) return;

    const size_t STR = (size_t)BB * LL * DD;
    size_t base = ((size_t)b * LL + l) * DD;
    float x[12];
#pragma unroll
    for (int i = 0; i < 12; i++) x[i] = in[base + lane + 32 * i];
    float s = 0.f;
#pragma unroll
    for (int i = 0; i < 12; i++) s += x[i];
#pragma unroll
    for (int o = 16; o > 0; o >>= 1) s += __shfl_xor_sync(0xffffffffu, s, o);
    float mu = s * (1.f / DD);
    float qv = 0.f;
#pragma unroll
    for (int i = 0; i < 12; i++) { float d = x[i] - mu; qv += d * d; }
#pragma unroll
    for (int o = 16; o > 0; o >>= 1) qv += __shfl_xor_sync(0xffffffffu, qv, o);
    float rstd = 1.f / sqrtf(qv * (1.f / DD) + 1e-5f);
#pragma unroll
    for (int i = 0; i < 12; i++) {
        int d = lane + 32 * i;
        float v = (x[i] - mu) * rstd * g[d] + be[d];
        __nv_bfloat16 b0, b1, b2;
        split3(v, b0, b1, b2);
        out[base + d] = b0; out[STR + base + d] = b1; out[2 * STR + base + d] = b2;
    }
}

// ---------------------------------------------------------------------------
__global__ __launch_bounds__(256)
void pred_kernel(const float* __restrict__ in, const float* __restrict__ g,
                 const float* __restrict__ be, const float* __restrict__ wl,
                 const float* __restrict__ bl, const int* __restrict__ tlen,
                 int* __restrict__ lns)
{
    int b = blockIdx.y;
    int l = blockIdx.x * 8 + (threadIdx.x >> 5);
    int lane = threadIdx.x & 31;
    if (l >= tlen[b]) { if (lane == 0) lns[b * LL + l] = 0; return; }

    size_t base = ((size_t)b * LL + l) * DD;
    float x[12];
#pragma unroll
    for (int i = 0; i < 12; i++) x[i] = in[base + lane + 32 * i];
    float s = 0.f;
#pragma unroll
    for (int i = 0; i < 12; i++) s += x[i];
#pragma unroll
    for (int o = 16; o > 0; o >>= 1) s += __shfl_xor_sync(0xffffffffu, s, o);
    float mu = s * (1.f / DD);
    float qv = 0.f;
#pragma unroll
    for (int i = 0; i < 12; i++) { float d = x[i] - mu; qv += d * d; }
#pragma unroll
    for (int o = 16; o > 0; o >>= 1) qv += __shfl_xor_sync(0xffffffffu, qv, o);
    float rstd = 1.f / sqrtf(qv * (1.f / DD) + 1e-5f);
    float p = 0.f;
#pragma unroll
    for (int i = 0; i < 12; i++) {
        int d = lane + 32 * i;
        p += ((x[i] - mu) * rstd * g[d] + be[d]) * wl[d];
    }
#pragma unroll
    for (int o = 16; o > 0; o >>= 1) p += __shfl_xor_sync(0xffffffffu, p, o);
    if (lane == 0) {
        float e = expf(p + bl[0]);
        float r = rintf(e);
        if (r > (float)MAXDUR) r = (float)MAXDUR;
        lns[b * LL + l] = (int)r;
    }
}

// ---------------------------------------------------------------------------
__global__ __launch_bounds__(1024)
void scan_kernel(const int* __restrict__ lns, int* __restrict__ csum,
                 int* __restrict__ tot, float* __restrict__ out_tail, int write_tail)
{
    __shared__ int s[1024];
    int b = blockIdx.x, t = threadIdx.x;
    s[t] = lns[b * LL + t];
    __syncthreads();
    for (int o = 1; o < 1024; o <<= 1) {
        int v = (t >= o) ? s[t - o] : 0;
        __syncthreads();
        s[t] += v;
        __syncthreads();
    }
    csum[b * LL + t] = s[t];
    if (t == 1023) {
        tot[b] = s[t];
        if (write_tail) out_tail[b] = (float)s[t];
    }
}

// ---------------------------------------------------------------------------
__global__ __launch_bounds__(256)
void gather_kernel(const float* __restrict__ y, const int* __restrict__ csum,
                   const int* __restrict__ tot, float* __restrict__ out)
{
    int b = blockIdx.y;
    int t = blockIdx.x * 8 + (threadIdx.x >> 5);
    int lane = threadIdx.x & 31;

    int idx = 0;
    if (lane == 0) {
        const int* c = csum + b * LL;
        int lo = 0, hi = LL;
        while (lo < hi) { int mid = (lo + hi) >> 1; if (c[mid] <= t) lo = mid + 1; else hi = mid; }
        idx = (lo < LL - 1) ? lo : (LL - 1);
    }
    idx = __shfl_sync(0xffffffffu, idx, 0);
    bool valid = t < tot[b];

    const float4* src = (const float4*)(y + ((size_t)b * LL + idx) * DD);
    float4*       dst = (float4*)(out + ((size_t)b * TOUT + t) * DD);
    float4 z = make_float4(0.f, 0.f, 0.f, 0.f);
#pragma unroll
    for (int i = 0; i < 3; i++) dst[lane + 32 * i] = valid ? src[lane + 32 * i] : z;
}

// ---------------------------------------------------------------------------
extern "C" void kernel_launch(void* const* d_in, const int* in_sizes, int n_in,
                              void* d_out, int out_size)
{
    const float* y    = (const float*)d_in[0];
    const int*   tlen = (const int*)  d_in[1];
    const float* w1a  = (const float*)d_in[2];
    const float* b1a  = (const float*)d_in[3];
    const float* w1b  = (const float*)d_in[4];
    const float* b1b  = (const float*)d_in[5];
    const float* g1   = (const float*)d_in[6];
    const float* be1  = (const float*)d_in[7];
    const float* w2a  = (const float*)d_in[8];
    const float* b2a  = (const float*)d_in[9];
    const float* w2b  = (const float*)d_in[10];
    const float* b2b  = (const float*)d_in[11];
    const float* g2   = (const float*)d_in[12];
    const float* be2  = (const float*)d_in[13];
    const float* wl   = (const float*)d_in[14];
    const float* bl   = (const float*)d_in[15];
    float* out = (float*)d_out;

    __nv_bfloat16 *ys, *h1as, *h1ns, *h2as, *w1as, *w1bs, *w2as, *w2bs;
    float *h1b, *h2b; int *lns, *csum, *tot;
    cudaGetSymbolAddress((void**)&ys,   g_ys);
    cudaGetSymbolAddress((void**)&h1as, g_h1as);
    cudaGetSymbolAddress((void**)&h1ns, g_h1ns);
    cudaGetSymbolAddress((void**)&h2as, g_h2as);
    cudaGetSymbolAddress((void**)&w1as, g_w1as);
    cudaGetSymbolAddress((void**)&w1bs, g_w1bs);
    cudaGetSymbolAddress((void**)&w2as, g_w2as);
    cudaGetSymbolAddress((void**)&w2bs, g_w2bs);
    cudaGetSymbolAddress((void**)&h1b,  g_h1b);
    cudaGetSymbolAddress((void**)&h2b,  g_h2b);
    cudaGetSymbolAddress((void**)&lns,  g_lns);
    cudaGetSymbolAddress((void**)&csum, g_csum);
    cudaGetSymbolAddress((void**)&tot,  g_tot);

    wsplit_kernel<<<FF, 256>>>(w1a, w1as, DD, FF);
    wsplit_kernel<<<DD, 256>>>(w1b, w1bs, FF, DD);
    wsplit_kernel<<<FF, 256>>>(w2a, w2as, DD, FF);
    wsplit_kernel<<<DD, 256>>>(w2b, w2bs, FF, DD);
    {
        size_t n = (size_t)BB * LL * DD;
        split_kernel<<<(unsigned)((n + 255) / 256), 256>>>(y, ys, n, n);
    }

    dim3 gA(LL / 128, FF / 64, BB);
    dim3 gB(LL / 128, DD / 64, BB);
    dim3 gR(LL / 8, BB);

    conv_mma_kernel<DD, FF, true ><<<gA, 512>>>(ys,   w1as, b1a, nullptr, h1as, tlen, 3);
    conv_mma_kernel<FF, DD, false><<<gB, 512>>>(h1as, w1bs, b1b, h1b, nullptr, tlen, 2);
    ln_split_kernel<<<gR, 256>>>(h1b, g1, be1, h1ns, tlen, 2);
    conv_mma_kernel<DD, FF, true ><<<gA, 512>>>(h1ns, w2as, b2a, nullptr, h2as, tlen, 1);
    conv_mma_kernel<FF, DD, false><<<gB, 512>>>(h2as, w2bs, b2b, h2b, nullptr, tlen, 0);
    pred_kernel<<<gR, 256>>>(h2b, g2, be2, wl, bl, tlen, lns);

    int write_tail = (out_size >= BB * TOUT * DD + BB) ? 1 : 0;
    scan_kernel<<<BB, 1024>>>(lns, csum, tot, out + (size_t)BB * TOUT * DD, write_tail);
    gather_kernel<<<dim3(TOUT / 8, BB), 256>>>(y, csum, tot, out);
}